// round 9
// baseline (speedup 1.0000x reference)
#include <cuda_runtime.h>

// EMA scan: out[b,t,d] = a*out[b,t-1,d] + (1-a)*x[b,t,d], out[b,-1,d]=0
// Shapes fixed: B=4, S=4096, D=2048, fp32.
//
// 4 L2-sized segments (1024 steps = 33.5MB). 5 launches:
//   K0:  P1(seg0) + last-CTA carry fixup
//   K1-3: fused P3(seg i) || P1(seg i+1) + fixup(i+1)   (role = blockIdx.z)
//   K4:  P3(seg3)
// Pass2 is gone: after P1 CTAs store chunk ends, the last-arriving CTA per
// (b, d-block) (atomic counter) chains the CPS=16 carries inline, updates
// the cross-segment running carry, and resets its counter (replay-safe).
// P3 reads x_i (L2-resident from the previous kernel's P1 part, __ldcs =
// last use) and writes out with __stcs (evict-first). Resident set during
// a fused kernel: x_i 33.5MB + x_{i+1} 33.5MB + evict-first out < 126MB L2.

#define B 4
#define S 4096
#define D 2048
#define SEG_T 1024            // timesteps per segment
#define NSEG (S / SEG_T)      // 4
#define CHUNK 64              // timesteps per chunk
#define CPS (SEG_T / CHUNK)   // 16 chunks per segment
#define TPB 256
#define NXB (D / TPB)         // 8 d-blocks

constexpr float ALPHA = 0.99f;
constexpr float ONEM  = 0.01f;

constexpr float pow_alpha(int n) {
    double r = 1.0;
    for (int i = 0; i < n; ++i) r *= 0.99;
    return (float)r;
}
constexpr float DEC = pow_alpha(CHUNK);   // alpha^64

// Scratch. g_carry parity-buffered: fixup(i+1) writes while P3(i) reads
// in the same fused kernel. g_cnt zero-initialized at load; each fixup CTA
// resets its slot -> deterministic across graph replays.
__device__ float g_ends [B * CPS * D];        // chunk-local end EMAs
__device__ float g_carry[2][B * CPS * D];     // carry at chunk start
__device__ float g_run  [B * D];              // running carry across segments
__device__ int   g_cnt  [B * NXB];            // P1 completion counters

// ---------------------------------------------------------------------------
// Carry chain for one segment's (b, d) lane (run by the fixup CTA).
// ---------------------------------------------------------------------------
__device__ __forceinline__ void fixup_chain(int seg, int b, int d) {
    float E = (seg == 0) ? 0.0f : g_run[b * D + d];
    float* carry = g_carry[seg & 1];

#pragma unroll
    for (int c0 = 0; c0 < CPS; c0 += 8) {
        float e[8];
#pragma unroll
        for (int j = 0; j < 8; ++j)
            e[j] = g_ends[((size_t)b * CPS + c0 + j) * D + d];
#pragma unroll
        for (int j = 0; j < 8; ++j) {
            carry[((size_t)b * CPS + c0 + j) * D + d] = E;
            E = fmaf(DEC, E, e[j]);
        }
    }
    g_run[b * D + d] = E;
}

// ---------------------------------------------------------------------------
// P1 work for one (seg, b, chunk, d-block) CTA: local EMA -> chunk end,
// then completion counting; the last CTA per (b, xblk) chains the carries.
// ---------------------------------------------------------------------------
__device__ __forceinline__ void p1_part(const float* __restrict__ x,
                                        int seg, int b, int c, int xblk) {
    const int tid = threadIdx.x;
    const int d = xblk * TPB + tid;

    const float* xp =
        x + ((size_t)b * S + (size_t)seg * SEG_T + (size_t)c * CHUNK) * D + d;

    float e = 0.0f;
#pragma unroll 4
    for (int t0 = 0; t0 < CHUNK; t0 += 8) {
        float v[8];
#pragma unroll
        for (int j = 0; j < 8; ++j) v[j] = xp[(size_t)(t0 + j) * D];
#pragma unroll
        for (int j = 0; j < 8; ++j) e = fmaf(ALPHA, e, ONEM * v[j]);
    }
    g_ends[((size_t)b * CPS + c) * D + d] = e;

    // Completion: last CTA for this (b, xblk) does the carry chain.
    __shared__ int s_last;
    __syncthreads();
    if (tid == 0) {
        __threadfence();   // release ends stores
        int old = atomicAdd(&g_cnt[b * NXB + xblk], 1);
        s_last = (old == CPS - 1);
    }
    __syncthreads();
    if (s_last) {
        __threadfence();   // acquire: all CTAs' ends visible
        fixup_chain(seg, b, d);
        if (tid == 0) g_cnt[b * NXB + xblk] = 0;   // replay-safe reset
    }
}

// ---------------------------------------------------------------------------
// P3 work: exact recurrence seeded with the carry; x read __ldcs (last use,
// L2-hot), out written __stcs (evict-first).
// ---------------------------------------------------------------------------
__device__ __forceinline__ void p3_part(const float* __restrict__ x,
                                        float* __restrict__ out,
                                        int seg, int b, int c, int xblk) {
    const int tid = threadIdx.x;
    const int d = xblk * TPB + tid;

    const size_t base =
        ((size_t)b * S + (size_t)seg * SEG_T + (size_t)c * CHUNK) * D + d;
    const float* xp = x + base;
    float* op = out + base;

    float ema = g_carry[seg & 1][((size_t)b * CPS + c) * D + d];

#pragma unroll 4
    for (int t0 = 0; t0 < CHUNK; t0 += 8) {
        float v[8];
#pragma unroll
        for (int j = 0; j < 8; ++j)
            v[j] = __ldcs(&xp[(size_t)(t0 + j) * D]);
        float r[8];
#pragma unroll
        for (int j = 0; j < 8; ++j) {
            ema = fmaf(ALPHA, ema, ONEM * v[j]);
            r[j] = ema;
        }
#pragma unroll
        for (int j = 0; j < 8; ++j)
            __stcs(&op[(size_t)(t0 + j) * D], r[j]);
    }
}

// ---------------------------------------------------------------------------
// Kernels. grid = (NXB, CPS, B) for the single-role kernels; (NXB, CPS, 2B)
// for the fused one (z < B: P3 of seg, z >= B: P1 of seg+1).
// ---------------------------------------------------------------------------
__global__ void __launch_bounds__(TPB) k_p1(const float* __restrict__ x,
                                            int seg) {
    p1_part(x, seg, blockIdx.z, blockIdx.y, blockIdx.x);
}

__global__ void __launch_bounds__(TPB) k_fused(const float* __restrict__ x,
                                               float* __restrict__ out,
                                               int seg) {
    const int z = blockIdx.z;
    if (z < B) p3_part(x, out, seg, z, blockIdx.y, blockIdx.x);
    else       p1_part(x, seg + 1, z - B, blockIdx.y, blockIdx.x);
}

__global__ void __launch_bounds__(TPB) k_p3(const float* __restrict__ x,
                                            float* __restrict__ out,
                                            int seg) {
    p3_part(x, out, seg, blockIdx.z, blockIdx.y, blockIdx.x);
}

extern "C" void kernel_launch(void* const* d_in, const int* in_sizes, int n_in,
                              void* d_out, int out_size) {
    const float* x = (const float*)d_in[0];
    float* out = (float*)d_out;

    dim3 gs(NXB, CPS, B);        // 512 CTAs
    dim3 gf(NXB, CPS, 2 * B);    // 1024 CTAs

    k_p1<<<gs, TPB>>>(x, 0);
    for (int i = 0; i + 1 < NSEG; ++i)
        k_fused<<<gf, TPB>>>(x, out, i);
    k_p3<<<gs, TPB>>>(x, out, NSEG - 1);
}

// round 10
// speedup vs baseline: 1.5484x; 1.5484x over previous
#include <cuda_runtime.h>

// EMA scan: out[b,t,d] = a*out[b,t-1,d] + (1-a)*x[b,t,d], out[b,-1,d]=0
// Shapes fixed: B=4, S=4096, D=2048, fp32.
//
// Single kernel. Each CTA owns 32 channels for the ENTIRE sequence, so the
// sequential carry never crosses a CTA boundary: x is read from DRAM exactly
// once and out written exactly once (268 MB, the traffic floor).
//
// CTA = 512 threads = 32 channels x 16 sub-chunks of 32 steps = one stage
// of 512 timesteps; 8 stages cover S. Per stage: load 32 values into
// registers (coalesced 128B, 32-deep MLP), local scan, publish sub-chunk
// ends to smem, ONE __syncthreads, each thread forms its carry as a
// weighted sum of preceding ends (alpha^(32i) constants; uniform trip count
// per warp; conflict-free), rescan from registers, store. Stage carry and
// ends are parity double-buffered => exactly 1 barrier per stage.
// 256 CTAs, 2 CTAs/SM (32 warps/SM), single co-resident wave.

#define B 4
#define S 4096
#define D 2048
#define CH 32                  // channels per CTA
#define SC 16                  // sub-chunks per stage
#define LEN 32                 // timesteps per sub-chunk
#define STAGE_T (SC * LEN)     // 512
#define NSTAGE (S / STAGE_T)   // 8
#define TPB (CH * SC)          // 512

constexpr float ALPHA = 0.99f;
constexpr float ONEM  = 0.01f;

constexpr float pow_alpha(int n) {
    double r = 1.0;
    for (int i = 0; i < n; ++i) r *= 0.99;
    return (float)r;
}

// DECP[i] = alpha^(32*i)
__constant__ float DECP[SC] = {
    pow_alpha(0),   pow_alpha(32),  pow_alpha(64),  pow_alpha(96),
    pow_alpha(128), pow_alpha(160), pow_alpha(192), pow_alpha(224),
    pow_alpha(256), pow_alpha(288), pow_alpha(320), pow_alpha(352),
    pow_alpha(384), pow_alpha(416), pow_alpha(448), pow_alpha(480)
};

__global__ void __launch_bounds__(TPB, 2)
ema_cta(const float* __restrict__ x, float* __restrict__ out) {
    __shared__ float s_ends[2][SC][CH];   // parity-buffered sub-chunk ends
    __shared__ float s_carry[2][CH];      // parity-buffered stage carry

    const int tid = threadIdx.x;
    const int ch = tid & (CH - 1);
    const int sc = tid >> 5;              // warp id == sub-chunk id
    const int d = blockIdx.x * CH + ch;
    const int b = blockIdx.y;

    if (tid < CH) s_carry[0][tid] = 0.0f;   // ordered by stage-0 barrier

    const float a = ALPHA, om = ONEM;

#pragma unroll 1
    for (int stage = 0; stage < NSTAGE; ++stage) {
        const int p = stage & 1;
        const size_t base =
            ((size_t)b * S + (size_t)stage * STAGE_T + (size_t)sc * LEN) * D + d;

        // Load sub-chunk into registers (32 independent coalesced loads).
        float v[LEN];
#pragma unroll
        for (int j = 0; j < LEN; ++j) v[j] = x[base + (size_t)j * D];

        // Local scan from zero -> sub-chunk end.
        float e = 0.0f;
#pragma unroll
        for (int j = 0; j < LEN; ++j) e = fmaf(a, e, om * v[j]);

        s_ends[p][sc][ch] = e;
        __syncthreads();   // the only barrier in the stage

        // Carry into this sub-chunk:
        //   E_sc = alpha^(32*sc) * E_stage + sum_{i<sc} alpha^(32*(sc-1-i)) * e_i
        float carry = DECP[sc] * s_carry[p][ch];
        for (int i = 0; i < sc; ++i)                    // uniform per warp
            carry = fmaf(DECP[sc - 1 - i], s_ends[p][i][ch], carry);

        // Last sub-chunk publishes next stage's carry (other parity slot;
        // safe: that slot's readers finished before this stage's barrier).
        if (sc == SC - 1)
            s_carry[p ^ 1][ch] = fmaf(DECP[1], carry, e);

        // Exact recurrence from registers, seeded with the carry.
        float ema = carry;
#pragma unroll
        for (int j = 0; j < LEN; ++j) {
            ema = fmaf(a, ema, om * v[j]);
            out[base + (size_t)j * D] = ema;
        }
    }
}

extern "C" void kernel_launch(void* const* d_in, const int* in_sizes, int n_in,
                              void* d_out, int out_size) {
    const float* x = (const float*)d_in[0];
    float* out = (float*)d_out;

    dim3 grid(D / CH, B);   // (64, 4) = 256 CTAs, single co-resident wave
    ema_cta<<<grid, TPB>>>(x, out);
}

// round 11
// speedup vs baseline: 1.6134x; 1.0420x over previous
#include <cuda_runtime.h>

// EMA scan: out[b,t,d] = a*out[b,t-1,d] + (1-a)*x[b,t,d], out[b,-1,d]=0
// Shapes fixed: B=4, S=4096, D=2048, fp32.
//
// Single kernel, CTA owns 32 channels for the whole sequence (traffic floor:
// x read once, out written once = 268 MB). Round-11 changes vs round-10:
//  - Software pipeline: LEN=16 + second register buffer; next stage's 16
//    loads are issued BEFORE the barrier and remain in flight through
//    barrier + carry + rescan, so DRAM never drains.
//  - Carry weighted-sum fully unrolled (15 independent LDS + predicated
//    FMAs) instead of a runtime-bounded serial chain.
// CTA = 512 thr = 32 channels x 16 sub-chunks of LEN=16 (stage = 256 steps,
// 16 stages). 1 barrier/stage, parity double-buffered smem. 256 CTAs,
// 2 CTAs/SM.

#define B 4
#define S 4096
#define D 2048
#define CH 32                  // channels per CTA
#define SC 16                  // sub-chunks per stage (== warps)
#define LEN 16                 // timesteps per sub-chunk
#define STAGE_T (SC * LEN)     // 256
#define NSTAGE (S / STAGE_T)   // 16
#define TPB (CH * SC)          // 512

constexpr float ALPHA = 0.99f;
constexpr float ONEM  = 0.01f;

constexpr float pow_alpha(int n) {
    double r = 1.0;
    for (int i = 0; i < n; ++i) r *= 0.99;
    return (float)r;
}

// DECP[i] = alpha^(LEN*i)
__constant__ float DECP[SC] = {
    pow_alpha(0),   pow_alpha(16),  pow_alpha(32),  pow_alpha(48),
    pow_alpha(64),  pow_alpha(80),  pow_alpha(96),  pow_alpha(112),
    pow_alpha(128), pow_alpha(144), pow_alpha(160), pow_alpha(176),
    pow_alpha(192), pow_alpha(208), pow_alpha(224), pow_alpha(240)
};

__global__ void __launch_bounds__(TPB, 2)
ema_cta(const float* __restrict__ x, float* __restrict__ out) {
    __shared__ float s_ends[2][SC][CH];   // parity-buffered sub-chunk ends
    __shared__ float s_carry[2][CH];      // parity-buffered stage carry

    const int tid = threadIdx.x;
    const int ch = tid & (CH - 1);
    const int sc = tid >> 5;              // warp id == sub-chunk id (uniform)
    const int d = blockIdx.x * CH + ch;
    const int b = blockIdx.y;

    if (tid < CH) s_carry[0][tid] = 0.0f;   // ordered by stage-0 barrier

    const float a = ALPHA, om = ONEM;

    // Prologue: load stage 0.
    float v[LEN], vn[LEN];
    {
        const size_t base0 = ((size_t)b * S + (size_t)sc * LEN) * D + d;
#pragma unroll
        for (int j = 0; j < LEN; ++j) v[j] = x[base0 + (size_t)j * D];
    }

#pragma unroll 1
    for (int stage = 0; stage < NSTAGE; ++stage) {
        const int p = stage & 1;
        const size_t base =
            ((size_t)b * S + (size_t)stage * STAGE_T + (size_t)sc * LEN) * D + d;

        // Prefetch next stage FIRST: 16 independent loads stay in flight
        // through the local scan, the barrier, and the carry section.
        if (stage + 1 < NSTAGE) {
            const size_t nb = base + (size_t)STAGE_T * D;
#pragma unroll
            for (int j = 0; j < LEN; ++j) vn[j] = x[nb + (size_t)j * D];
        }

        // Local scan from zero -> sub-chunk end.
        float e = 0.0f;
#pragma unroll
        for (int j = 0; j < LEN; ++j) e = fmaf(a, e, om * v[j]);

        s_ends[p][sc][ch] = e;
        __syncthreads();   // the only barrier in the stage

        // Carry into this sub-chunk: fully unrolled; 15 independent LDS,
        // out-of-range terms predicated to weight 0.
        float carry = DECP[sc] * s_carry[p][ch];
#pragma unroll
        for (int i = 0; i < SC - 1; ++i) {
            const float ei = s_ends[p][i][ch];
            const int idx = sc - 1 - i;
            const float w = (idx >= 0) ? DECP[idx] : 0.0f;
            carry = fmaf(w, ei, carry);
        }

        // Last sub-chunk publishes next stage's carry (other parity slot).
        if (sc == SC - 1)
            s_carry[p ^ 1][ch] = fmaf(DECP[1], carry, e);

        // Exact recurrence from registers, seeded with the carry.
        float ema = carry;
#pragma unroll
        for (int j = 0; j < LEN; ++j) {
            ema = fmaf(a, ema, om * v[j]);
            out[base + (size_t)j * D] = ema;
        }

#pragma unroll
        for (int j = 0; j < LEN; ++j) v[j] = vn[j];
    }
}

extern "C" void kernel_launch(void* const* d_in, const int* in_sizes, int n_in,
                              void* d_out, int out_size) {
    const float* x = (const float*)d_in[0];
    float* out = (float*)d_out;

    dim3 grid(D / CH, B);   // (64, 4) = 256 CTAs
    ema_cta<<<grid, TPB>>>(x, out);
}

// round 12
// speedup vs baseline: 1.6735x; 1.0372x over previous
#include <cuda_runtime.h>

// EMA scan: out[b,t,d] = a*out[b,t-1,d] + (1-a)*x[b,t,d], out[b,-1,d]=0
// Shapes fixed: B=4, S=4096, D=2048, fp32.
//
// Single kernel, CTA owns 32 channels for the whole sequence (traffic
// floor: x read once, out written once). Round-12 vs round-11:
//  - stage loop hand-unrolled x2 (v0/v1 ping-pong): no register copies,
//    parity indices become compile-time constants
//  - base pointers advanced by constant stride (no per-stage multiply)
//  - __ldcs on x (use-once), __stcs on out (never re-read): L2 evict-first
// CTA = 512 thr = 32 channels x 16 sub-chunks of LEN=16; 16 stages,
// 1 barrier/stage, parity double-buffered smem; 256 CTAs, 2 CTAs/SM.

#define B 4
#define S 4096
#define D 2048
#define CH 32                  // channels per CTA
#define SC 16                  // sub-chunks per stage (== warps)
#define LEN 16                 // timesteps per sub-chunk
#define STAGE_T (SC * LEN)     // 256
#define NSTAGE (S / STAGE_T)   // 16 (even, required by the x2 unroll)
#define TPB (CH * SC)          // 512

constexpr float ALPHA = 0.99f;
constexpr float ONEM  = 0.01f;

constexpr float pow_alpha(int n) {
    double r = 1.0;
    for (int i = 0; i < n; ++i) r *= 0.99;
    return (float)r;
}

// DECP[i] = alpha^(LEN*i)
__constant__ float DECP[SC] = {
    pow_alpha(0),   pow_alpha(16),  pow_alpha(32),  pow_alpha(48),
    pow_alpha(64),  pow_alpha(80),  pow_alpha(96),  pow_alpha(112),
    pow_alpha(128), pow_alpha(144), pow_alpha(160), pow_alpha(176),
    pow_alpha(192), pow_alpha(208), pow_alpha(224), pow_alpha(240)
};

// One stage: prefetch next tile into VNXT, scan VCUR, exchange carries
// (parity P compile-time), rescan + store. xn/op are this thread's
// sub-chunk base pointers for the NEXT stage's x and THIS stage's out.
#define STAGE_BODY(P, VCUR, VNXT, xn, op, do_pf)                          \
    {                                                                     \
        if (do_pf) {                                                      \
            _Pragma("unroll")                                             \
            for (int j = 0; j < LEN; ++j)                                 \
                VNXT[j] = __ldcs(&(xn)[(size_t)j * D]);                   \
        }                                                                 \
        float e = 0.0f;                                                   \
        _Pragma("unroll")                                                 \
        for (int j = 0; j < LEN; ++j)                                     \
            e = fmaf(ALPHA, e, ONEM * VCUR[j]);                           \
        s_ends[P][sc][ch] = e;                                            \
        __syncthreads();                                                  \
        float carry = DECP[sc] * s_carry[P][ch];                          \
        _Pragma("unroll")                                                 \
        for (int i = 0; i < SC - 1; ++i) {                                \
            const float ei = s_ends[P][i][ch];                            \
            const int idx = sc - 1 - i;                                   \
            const float w = (idx >= 0) ? DECP[idx] : 0.0f;                \
            carry = fmaf(w, ei, carry);                                   \
        }                                                                 \
        if (sc == SC - 1)                                                 \
            s_carry[(P) ^ 1][ch] = fmaf(DECP[1], carry, e);               \
        float ema = carry;                                                \
        _Pragma("unroll")                                                 \
        for (int j = 0; j < LEN; ++j) {                                   \
            ema = fmaf(ALPHA, ema, ONEM * VCUR[j]);                       \
            __stcs(&(op)[(size_t)j * D], ema);                            \
        }                                                                 \
    }

__global__ void __launch_bounds__(TPB, 2)
ema_cta(const float* __restrict__ x, float* __restrict__ out) {
    __shared__ float s_ends[2][SC][CH];   // parity-buffered sub-chunk ends
    __shared__ float s_carry[2][CH];      // parity-buffered stage carry

    const int tid = threadIdx.x;
    const int ch = tid & (CH - 1);
    const int sc = tid >> 5;              // warp id == sub-chunk id (uniform)
    const int d = blockIdx.x * CH + ch;
    const int b = blockIdx.y;

    if (tid < CH) s_carry[0][tid] = 0.0f;   // ordered by stage-0 barrier

    // This thread's sub-chunk column base (stage 0); advance by constant.
    const size_t col = (size_t)b * S * D + (size_t)sc * LEN * D + d;
    const float* xp = x + col;
    float* op = out + col;
    const size_t STRIDE = (size_t)STAGE_T * D;

    float v0[LEN], v1[LEN];
#pragma unroll
    for (int j = 0; j < LEN; ++j) v0[j] = __ldcs(&xp[(size_t)j * D]);

#pragma unroll 1
    for (int st = 0; st < NSTAGE; st += 2) {
        // Stage st (parity 0): consume v0, prefetch v1.
        STAGE_BODY(0, v0, v1, xp + STRIDE, op, true)
        xp += STRIDE; op += STRIDE;

        // Stage st+1 (parity 1): consume v1, prefetch v0 (skip on last).
        const bool pf = (st + 2 < NSTAGE);
        STAGE_BODY(1, v1, v0, xp + STRIDE, op, pf)
        xp += STRIDE; op += STRIDE;
    }
}

extern "C" void kernel_launch(void* const* d_in, const int* in_sizes, int n_in,
                              void* d_out, int out_size) {
    const float* x = (const float*)d_in[0];
    float* out = (float*)d_out;

    dim3 grid(D / CH, B);   // (64, 4) = 256 CTAs
    ema_cta<<<grid, TPB>>>(x, out);
}